// round 7
// baseline (speedup 1.0000x reference)
#include <cuda_runtime.h>
#include <cuda_bf16.h>
#include <cstdint>

#define NODES    100000
#define NODES_PAD 100096          // 782 * 128
#define C        256
#define ASTRIDE  512              // g_A row: [hi(256) | lo(256)]
#define KSPL     768              // logical K = 3 * 256 (hi*hi + hi*lo + lo*hi)
#define GRAPHS   64
#define OUTC     10
#define EMAX     1600000
#define NB1024   ((NODES + 1023) / 1024)

// ---------------- scratch (static device globals; no allocation) ----------
__device__ __align__(16) __nv_bfloat16 g_A[(size_t)NODES_PAD * ASTRIDE];
__device__ __align__(16) __nv_bfloat16 g_B[(size_t)C * KSPL];   // [n][k] K=768
__device__ __align__(16) uint32_t g_hsb[(size_t)NODES_PAD * (C / 2)]; // bf16x2
__device__ float g_dinv[NODES];
__device__ int   g_degi[NODES];
__device__ int   g_rowptr[NODES + 1];
__device__ int   g_cursor[NODES];
__device__ int   g_elist[EMAX];
__device__ int   g_bsum[NB1024 + 1];
__device__ float g_sums[GRAPHS * C];
__device__ float g_counts[GRAPHS];
__device__ int   g_is64;

// ---------------- helpers ------------------------------------------------
__device__ __forceinline__ int load_idx(const void* p, long long i, int is64) {
    if (is64) return (int)((const long long*)p)[i];
    return ((const int*)p)[i];
}

__device__ __forceinline__ void mma16816(float* c, const uint32_t* a,
                                         const uint32_t* b) {
    asm volatile(
        "mma.sync.aligned.m16n8k16.row.col.f32.bf16.bf16.f32 "
        "{%0,%1,%2,%3}, {%4,%5,%6,%7}, {%8,%9}, {%0,%1,%2,%3};"
        : "+f"(c[0]), "+f"(c[1]), "+f"(c[2]), "+f"(c[3])
        : "r"(a[0]), "r"(a[1]), "r"(a[2]), "r"(a[3]), "r"(b[0]), "r"(b[1]));
}

__device__ __forceinline__ uint32_t smem_u32(const void* p) {
    uint32_t a;
    asm("{ .reg .u64 t; cvta.to.shared.u64 t, %1; cvt.u32.u64 %0, t; }"
        : "=r"(a) : "l"(p));
    return a;
}
__device__ __forceinline__ void cp16(uint32_t dst, const void* src) {
    asm volatile("cp.async.ca.shared.global [%0], [%1], 16;"
                 :: "r"(dst), "l"(src) : "memory");
}
#define CP_COMMIT() asm volatile("cp.async.commit_group;" ::: "memory")
#define CP_WAIT(N)  asm volatile("cp.async.wait_group %0;" :: "n"(N) : "memory")

// ---------------------------------------------------------------------------
__global__ void detect_kernel(const int* __restrict__ ei32) {
    if (threadIdx.x == 0 && blockIdx.x == 0) {
        int nz = 0;
        #pragma unroll
        for (int i = 1; i < 256; i += 2) nz |= (ei32[i] != 0);
        g_is64 = (nz == 0) ? 1 : 0;
    }
}

__global__ void init_kernel(int n) {
    int i = blockIdx.x * blockDim.x + threadIdx.x;
    if (i < n) g_degi[i] = 0;
    if (i < GRAPHS * C) g_sums[i] = 0.f;
    if (i < GRAPHS) g_counts[i] = 0.f;
}

__global__ void degi_kernel(const void* __restrict__ ei, int E) {
    int i = blockIdx.x * blockDim.x + threadIdx.x;
    if (i >= E) return;
    int d = load_idx(ei, (long long)E + i, g_is64);
    atomicAdd(&g_degi[d], 1);
}

// ---------------- hierarchical scan ----------------------------------------
__global__ void scan1_kernel(int n) {
    __shared__ int wsum[32];
    int t = threadIdx.x;
    int i = blockIdx.x * 1024 + t;
    int v = (i < n) ? g_degi[i] : 0;
    int lane = t & 31, w = t >> 5;
    int inc = v;
    #pragma unroll
    for (int d = 1; d < 32; d <<= 1) {
        int u = __shfl_up_sync(0xFFFFFFFFu, inc, d);
        if (lane >= d) inc += u;
    }
    if (lane == 31) wsum[w] = inc;
    __syncthreads();
    if (w == 0) {
        int x = wsum[lane];
        #pragma unroll
        for (int d = 1; d < 32; d <<= 1) {
            int u = __shfl_up_sync(0xFFFFFFFFu, x, d);
            if (lane >= d) x += u;
        }
        wsum[lane] = x;
    }
    __syncthreads();
    int excl = inc - v + (w ? wsum[w - 1] : 0);
    if (i < n) g_rowptr[i] = excl;
    if (t == 1023) g_bsum[blockIdx.x] = excl + v;
}

__global__ void scan2_kernel(int nb) {
    __shared__ int wsum[32];
    int t = threadIdx.x;                     // 1024 threads
    int v = (t < nb) ? g_bsum[t] : 0;
    int lane = t & 31, w = t >> 5;
    int inc = v;
    #pragma unroll
    for (int d = 1; d < 32; d <<= 1) {
        int u = __shfl_up_sync(0xFFFFFFFFu, inc, d);
        if (lane >= d) inc += u;
    }
    if (lane == 31) wsum[w] = inc;
    __syncthreads();
    if (w == 0) {
        int x = wsum[lane];
        #pragma unroll
        for (int d = 1; d < 32; d <<= 1) {
            int u = __shfl_up_sync(0xFFFFFFFFu, x, d);
            if (lane >= d) x += u;
        }
        wsum[lane] = x;
    }
    __syncthreads();
    int excl = inc - v + (w ? wsum[w - 1] : 0);
    if (t < nb) g_bsum[t] = excl;
}

__global__ void scan3_kernel(int n) {
    int i = blockIdx.x * blockDim.x + threadIdx.x;
    if (i >= n) return;
    int d = g_degi[i];
    int r = g_rowptr[i] + g_bsum[i >> 10];
    g_rowptr[i] = r;
    g_cursor[i] = r;
    g_dinv[i] = rsqrtf((float)d + 1.f);
    if (i == n - 1) g_rowptr[n] = r + d;
}

__global__ void place_kernel(const void* __restrict__ ei, int E) {
    int e = blockIdx.x * blockDim.x + threadIdx.x;
    if (e >= E) return;
    int is64 = g_is64;
    int src = load_idx(ei, e, is64);
    int dst = load_idx(ei, (long long)E + e, is64);
    int pos = atomicAdd(&g_cursor[dst], 1);
    g_elist[pos] = src;
}

// ---------------------------------------------------------------------------
// A = [bf16(x*dinv) | bf16(residual)], rows padded with zeros
__global__ void convert_kernel(const float* __restrict__ x, int n) {
    long long idx = (long long)blockIdx.x * blockDim.x + threadIdx.x;
    if (idx >= (long long)NODES_PAD * 128) return;
    int row = (int)(idx >> 7);
    int p = (int)(idx & 127);
    int c = p * 2;
    float v0 = 0.f, v1 = 0.f;
    if (row < n) {
        float d = g_dinv[row];
        v0 = x[(size_t)row * C + c] * d;
        v1 = x[(size_t)row * C + c + 1] * d;
    }
    __nv_bfloat16 h0 = __float2bfloat16(v0);
    __nv_bfloat16 h1 = __float2bfloat16(v1);
    __nv_bfloat162 hi2; hi2.x = h0; hi2.y = h1;
    __nv_bfloat162 lo2;
    lo2.x = __float2bfloat16(v0 - __bfloat162float(h0));
    lo2.y = __float2bfloat16(v1 - __bfloat162float(h1));
    __nv_bfloat162* base = (__nv_bfloat162*)(g_A + (size_t)row * ASTRIDE);
    base[p]       = hi2;
    base[128 + p] = lo2;
}

// B rows n: [W_hi(k) | W_lo(k) | W_hi(k)], K-major [n][k], K=768
__global__ void bbuild_kernel(const float* __restrict__ W1) {
    int idx = blockIdx.x * blockDim.x + threadIdx.x;
    if (idx >= C * C) return;
    int nn = idx >> 8, k = idx & 255;
    float w = W1[(size_t)k * C + nn];
    __nv_bfloat16 hi = __float2bfloat16(w);
    __nv_bfloat16 lo = __float2bfloat16(w - __bfloat162float(hi));
    g_B[(size_t)nn * KSPL + k]       = hi;
    g_B[(size_t)nn * KSPL + 256 + k] = lo;
    g_B[(size_t)nn * KSPL + 512 + k] = hi;
}

// ---------------------------------------------------------------------------
// bf16 mma.sync GEMM with cp.async double buffering; epilogue packs bf16x2.
#define APAD 72
#define STG_ELEMS ((128 + 256) * APAD)

__device__ __forceinline__ void load_stage(uint32_t sbase, int tid, int m0,
                                           int kc, int s) {
    uint32_t As = sbase + (uint32_t)(s * STG_ELEMS) * 2;
    uint32_t Bs = As + 128 * APAD * 2;
    int aoff = (kc & 3) * 64 + ((kc >= 8) ? 256 : 0);   // hi chunks reused
    const __nv_bfloat16* Ab = g_A + (size_t)m0 * ASTRIDE + aoff;
    #pragma unroll
    for (int i = 0; i < 4; i++) {
        int u = tid + i * 256;
        int r = u >> 3, o = u & 7;
        cp16(As + (uint32_t)(r * APAD + o * 8) * 2,
             Ab + (size_t)r * ASTRIDE + o * 8);
    }
    const __nv_bfloat16* Bb = g_B + kc * 64;
    #pragma unroll
    for (int i = 0; i < 8; i++) {
        int u = tid + i * 256;
        int r = u >> 3, o = u & 7;
        cp16(Bs + (uint32_t)(r * APAD + o * 8) * 2,
             Bb + (size_t)r * KSPL + o * 8);
    }
    CP_COMMIT();
}

__global__ void __launch_bounds__(256) gemm_mma_kernel() {
    extern __shared__ __nv_bfloat16 smem[];

    int tid = threadIdx.x;
    int wid = tid >> 5, lane = tid & 31;
    int g = lane >> 2, tir = lane & 3;
    int wm = wid & 1, wn = wid >> 1;          // warp grid 2 x 4
    int m0 = blockIdx.x * 128;

    uint32_t sbase = smem_u32(smem);
    const int NKC = KSPL / 64;                // 12 chunks

    float c[4][8][4];
    #pragma unroll
    for (int mt = 0; mt < 4; mt++)
        #pragma unroll
        for (int nt = 0; nt < 8; nt++)
            #pragma unroll
            for (int q = 0; q < 4; q++) c[mt][nt][q] = 0.f;

    load_stage(sbase, tid, m0, 0, 0);

    for (int kc = 0; kc < NKC; kc++) {
        if (kc + 1 < NKC) {
            load_stage(sbase, tid, m0, kc + 1, (kc + 1) & 1);
            CP_WAIT(1);
        } else {
            CP_WAIT(0);
        }
        __syncthreads();

        const __nv_bfloat16* As = smem + (kc & 1) * STG_ELEMS;
        const __nv_bfloat16* Bs = As + 128 * APAD;

        #pragma unroll
        for (int ks = 0; ks < 4; ks++) {
            int kof = ks * 16 + tir * 2;
            uint32_t a[4][4];
            #pragma unroll
            for (int mt = 0; mt < 4; mt++) {
                int base = (wm * 64 + mt * 16 + g) * APAD + kof;
                a[mt][0] = *(const uint32_t*)(As + base);
                a[mt][1] = *(const uint32_t*)(As + base + 8 * APAD);
                a[mt][2] = *(const uint32_t*)(As + base + 8);
                a[mt][3] = *(const uint32_t*)(As + base + 8 * APAD + 8);
            }
            uint32_t b[8][2];
            #pragma unroll
            for (int nt = 0; nt < 8; nt++) {
                int base = (wn * 64 + nt * 8 + g) * APAD + kof;
                b[nt][0] = *(const uint32_t*)(Bs + base);
                b[nt][1] = *(const uint32_t*)(Bs + base + 8);
            }
            #pragma unroll
            for (int mt = 0; mt < 4; mt++)
                #pragma unroll
                for (int nt = 0; nt < 8; nt++)
                    mma16816(c[mt][nt], a[mt], b[nt]);
        }
        __syncthreads();
    }

    // epilogue: pack fp32 pair -> bf16x2, single 4B store per fragment half
    #pragma unroll
    for (int mt = 0; mt < 4; mt++) {
        int row = m0 + wm * 64 + mt * 16 + g;
        #pragma unroll
        for (int nt = 0; nt < 8; nt++) {
            int col2 = wn * 32 + nt * 4 + tir;   // (col)/2, col even
            __nv_bfloat162 p0 = __float22bfloat162_rn(
                make_float2(c[mt][nt][0], c[mt][nt][1]));
            __nv_bfloat162 p1 = __float22bfloat162_rn(
                make_float2(c[mt][nt][2], c[mt][nt][3]));
            g_hsb[(size_t)row * (C / 2) + col2]       = *(uint32_t*)&p0;
            g_hsb[(size_t)(row + 8) * (C / 2) + col2] = *(uint32_t*)&p1;
        }
    }
}

// ---------------------------------------------------------------------------
// fused CSR gather + relu + mean-pool-sum: one block (128 thr) per dst node.
// thread t owns channels (2t, 2t+1) as one bf16x2 word per row.
__global__ void __launch_bounds__(128) gather_pool_kernel(
        const void* __restrict__ batch, const float* __restrict__ b1, int n) {
    int i = blockIdx.x;
    int t = threadIdx.x;                 // 0..127
    int r0 = g_rowptr[i], r1 = g_rowptr[i + 1];

    // self-loop term
    uint32_t w = g_hsb[(size_t)i * 128 + t];
    float2 f = __bfloat1622float2(*(__nv_bfloat162*)&w);
    float a0x = f.x, a0y = f.y;
    float a1x = 0.f, a1y = 0.f, a2x = 0.f, a2y = 0.f, a3x = 0.f, a3y = 0.f;

    int j = r0;
    for (; j + 4 <= r1; j += 4) {
        int s0 = g_elist[j],     s1 = g_elist[j + 1];
        int s2 = g_elist[j + 2], s3 = g_elist[j + 3];
        uint32_t w0 = g_hsb[(size_t)s0 * 128 + t];
        uint32_t w1 = g_hsb[(size_t)s1 * 128 + t];
        uint32_t w2 = g_hsb[(size_t)s2 * 128 + t];
        uint32_t w3 = g_hsb[(size_t)s3 * 128 + t];
        float2 f0 = __bfloat1622float2(*(__nv_bfloat162*)&w0);
        float2 f1 = __bfloat1622float2(*(__nv_bfloat162*)&w1);
        float2 f2 = __bfloat1622float2(*(__nv_bfloat162*)&w2);
        float2 f3 = __bfloat1622float2(*(__nv_bfloat162*)&w3);
        a0x += f0.x; a0y += f0.y;
        a1x += f1.x; a1y += f1.y;
        a2x += f2.x; a2y += f2.y;
        a3x += f3.x; a3y += f3.y;
    }
    for (; j < r1; j++) {
        uint32_t wj = g_hsb[(size_t)g_elist[j] * 128 + t];
        float2 fj = __bfloat1622float2(*(__nv_bfloat162*)&wj);
        a0x += fj.x; a0y += fj.y;
    }

    float di = g_dinv[i];
    float vx = fmaxf(di * ((a0x + a1x) + (a2x + a3x)) + b1[2 * t], 0.f);
    float vy = fmaxf(di * ((a0y + a1y) + (a2y + a3y)) + b1[2 * t + 1], 0.f);

    int gid = load_idx(batch, i, g_is64);
    atomicAdd(&g_sums[gid * C + 2 * t], vx);
    atomicAdd(&g_sums[gid * C + 2 * t + 1], vy);
}

// ---------------------------------------------------------------------------
__global__ void bcount_kernel(const void* __restrict__ batch, int n) {
    int i = blockIdx.x * blockDim.x + threadIdx.x;
    if (i >= n) return;
    atomicAdd(&g_counts[load_idx(batch, i, g_is64)], 1.f);
}

__global__ void final_kernel(const float* __restrict__ W2,
                             const float* __restrict__ b2,
                             float* __restrict__ out) {
    int t = threadIdx.x;
    if (t >= GRAPHS * OUTC) return;
    int g = t / OUTC, o = t % OUTC;
    float s = 0.f;
    #pragma unroll 8
    for (int k = 0; k < C; k++)
        s += g_sums[g * C + k] * W2[k * OUTC + o];
    out[t] = s / fmaxf(g_counts[g], 1.f) + b2[o];
}

// ---------------------------------------------------------------------------
extern "C" void kernel_launch(void* const* d_in, const int* in_sizes, int n_in,
                              void* d_out, int out_size) {
    const float* x     = (const float*)d_in[0];
    const void*  ei    = d_in[1];
    const void*  batch = d_in[2];
    const float* W1    = (const float*)d_in[3];
    const float* b1    = (const float*)d_in[4];
    const float* W2    = (const float*)d_in[5];
    const float* b2    = (const float*)d_in[6];
    float* out = (float*)d_out;

    int n = in_sizes[0] / C;    // 100000
    int E = in_sizes[1] / 2;    // 1600000
    int nb = (n + 1023) / 1024;

    detect_kernel<<<1, 32>>>((const int*)ei);
    init_kernel<<<(n + 255) / 256, 256>>>(n);
    degi_kernel<<<(E + 255) / 256, 256>>>(ei, E);
    scan1_kernel<<<nb, 1024>>>(n);
    scan2_kernel<<<1, 1024>>>(nb);
    scan3_kernel<<<(n + 255) / 256, 256>>>(n);

    convert_kernel<<<(NODES_PAD * 128 + 255) / 256, 256>>>(x, n);
    bbuild_kernel<<<256, 256>>>(W1);

    static const int SMEM_BYTES = 2 * STG_ELEMS * 2;   // 110592
    cudaFuncSetAttribute(gemm_mma_kernel,
                         cudaFuncAttributeMaxDynamicSharedMemorySize, SMEM_BYTES);
    gemm_mma_kernel<<<NODES_PAD / 128, 256, SMEM_BYTES>>>();

    place_kernel<<<(E + 255) / 256, 256>>>(ei, E);
    bcount_kernel<<<(n + 255) / 256, 256>>>(batch, n);
    gather_pool_kernel<<<n, 128>>>(batch, b1, n);
    final_kernel<<<1, 640>>>(W2, b2, out);
}

// round 8
// speedup vs baseline: 2.1216x; 2.1216x over previous
#include <cuda_runtime.h>
#include <cuda_bf16.h>
#include <cstdint>

#define NODES    100000
#define NODES_PAD 100096          // 782 * 128
#define C        256
#define ASTRIDE  512              // g_A row: [hi(256) | lo(256)]
#define KSPL     768              // logical K = 3 * 256 (hi*hi + hi*lo + lo*hi)
#define GRAPHS   64
#define OUTC     10
#define EMAX     1600000
#define NB1024   ((NODES + 1023) / 1024)

// ---------------- scratch (static device globals; no allocation) ----------
__device__ __align__(16) __nv_bfloat16 g_A[(size_t)NODES_PAD * ASTRIDE];
__device__ __align__(16) __nv_bfloat16 g_B[(size_t)C * KSPL];   // [n][k] K=768
__device__ __align__(16) uint32_t g_hsb[(size_t)NODES_PAD * (C / 2)]; // bf16x2
__device__ float g_dinv[NODES];
__device__ int   g_degi[NODES];
__device__ int   g_rowptr[NODES + 1];
__device__ int   g_cursor[NODES];
__device__ int   g_elist[EMAX];
__device__ int   g_bsum[NB1024 + 1];
__device__ float g_sums[GRAPHS * C];
__device__ float g_counts[GRAPHS];
__device__ int   g_is64;

// ---------------- helpers ------------------------------------------------
__device__ __forceinline__ int load_idx(const void* p, long long i, int is64) {
    if (is64) return (int)((const long long*)p)[i];
    return ((const int*)p)[i];
}

__device__ __forceinline__ void mma16816(float* c, const uint32_t* a,
                                         const uint32_t* b) {
    asm volatile(
        "mma.sync.aligned.m16n8k16.row.col.f32.bf16.bf16.f32 "
        "{%0,%1,%2,%3}, {%4,%5,%6,%7}, {%8,%9}, {%0,%1,%2,%3};"
        : "+f"(c[0]), "+f"(c[1]), "+f"(c[2]), "+f"(c[3])
        : "r"(a[0]), "r"(a[1]), "r"(a[2]), "r"(a[3]), "r"(b[0]), "r"(b[1]));
}

__device__ __forceinline__ uint32_t smem_u32(const void* p) {
    uint32_t a;
    asm("{ .reg .u64 t; cvta.to.shared.u64 t, %1; cvt.u32.u64 %0, t; }"
        : "=r"(a) : "l"(p));
    return a;
}
__device__ __forceinline__ void cp16(uint32_t dst, const void* src) {
    asm volatile("cp.async.ca.shared.global [%0], [%1], 16;"
                 :: "r"(dst), "l"(src) : "memory");
}
#define CP_COMMIT() asm volatile("cp.async.commit_group;" ::: "memory")
#define CP_WAIT(N)  asm volatile("cp.async.wait_group %0;" :: "n"(N) : "memory")

// ---------------------------------------------------------------------------
__global__ void detect_kernel(const int* __restrict__ ei32) {
    if (threadIdx.x == 0 && blockIdx.x == 0) {
        int nz = 0;
        #pragma unroll
        for (int i = 1; i < 256; i += 2) nz |= (ei32[i] != 0);
        g_is64 = (nz == 0) ? 1 : 0;
    }
}

__global__ void init_kernel(int n) {
    int i = blockIdx.x * blockDim.x + threadIdx.x;
    if (i < n) g_degi[i] = 0;
    if (i < GRAPHS * C) g_sums[i] = 0.f;
    if (i < GRAPHS) g_counts[i] = 0.f;
}

__global__ void degi_kernel(const void* __restrict__ ei, int E) {
    int i = blockIdx.x * blockDim.x + threadIdx.x;
    if (i >= E) return;
    int d = load_idx(ei, (long long)E + i, g_is64);
    atomicAdd(&g_degi[d], 1);
}

// ---------------- hierarchical scan ----------------------------------------
__global__ void scan1_kernel(int n) {
    __shared__ int wsum[32];
    int t = threadIdx.x;
    int i = blockIdx.x * 1024 + t;
    int v = (i < n) ? g_degi[i] : 0;
    int lane = t & 31, w = t >> 5;
    int inc = v;
    #pragma unroll
    for (int d = 1; d < 32; d <<= 1) {
        int u = __shfl_up_sync(0xFFFFFFFFu, inc, d);
        if (lane >= d) inc += u;
    }
    if (lane == 31) wsum[w] = inc;
    __syncthreads();
    if (w == 0) {
        int x = wsum[lane];
        #pragma unroll
        for (int d = 1; d < 32; d <<= 1) {
            int u = __shfl_up_sync(0xFFFFFFFFu, x, d);
            if (lane >= d) x += u;
        }
        wsum[lane] = x;
    }
    __syncthreads();
    int excl = inc - v + (w ? wsum[w - 1] : 0);
    if (i < n) g_rowptr[i] = excl;
    if (t == 1023) g_bsum[blockIdx.x] = excl + v;
}

__global__ void scan2_kernel(int nb) {
    __shared__ int wsum[32];
    int t = threadIdx.x;                     // 1024 threads
    int v = (t < nb) ? g_bsum[t] : 0;
    int lane = t & 31, w = t >> 5;
    int inc = v;
    #pragma unroll
    for (int d = 1; d < 32; d <<= 1) {
        int u = __shfl_up_sync(0xFFFFFFFFu, inc, d);
        if (lane >= d) inc += u;
    }
    if (lane == 31) wsum[w] = inc;
    __syncthreads();
    if (w == 0) {
        int x = wsum[lane];
        #pragma unroll
        for (int d = 1; d < 32; d <<= 1) {
            int u = __shfl_up_sync(0xFFFFFFFFu, x, d);
            if (lane >= d) x += u;
        }
        wsum[lane] = x;
    }
    __syncthreads();
    int excl = inc - v + (w ? wsum[w - 1] : 0);
    if (t < nb) g_bsum[t] = excl;
}

__global__ void scan3_kernel(int n) {
    int i = blockIdx.x * blockDim.x + threadIdx.x;
    if (i >= n) return;
    int d = g_degi[i];
    int r = g_rowptr[i] + g_bsum[i >> 10];
    g_rowptr[i] = r;
    g_cursor[i] = r;
    g_dinv[i] = rsqrtf((float)d + 1.f);
    if (i == n - 1) g_rowptr[n] = r + d;
}

__global__ void place_kernel(const void* __restrict__ ei, int E) {
    int e = blockIdx.x * blockDim.x + threadIdx.x;
    if (e >= E) return;
    int is64 = g_is64;
    int src = load_idx(ei, e, is64);
    int dst = load_idx(ei, (long long)E + e, is64);
    int pos = atomicAdd(&g_cursor[dst], 1);
    g_elist[pos] = src;
}

// ---------------------------------------------------------------------------
// A = [bf16(x*dinv) | bf16(residual)], rows padded with zeros
__global__ void convert_kernel(const float* __restrict__ x, int n) {
    long long idx = (long long)blockIdx.x * blockDim.x + threadIdx.x;
    if (idx >= (long long)NODES_PAD * 128) return;
    int row = (int)(idx >> 7);
    int p = (int)(idx & 127);
    int c = p * 2;
    float v0 = 0.f, v1 = 0.f;
    if (row < n) {
        float d = g_dinv[row];
        v0 = x[(size_t)row * C + c] * d;
        v1 = x[(size_t)row * C + c + 1] * d;
    }
    __nv_bfloat16 h0 = __float2bfloat16(v0);
    __nv_bfloat16 h1 = __float2bfloat16(v1);
    __nv_bfloat162 hi2; hi2.x = h0; hi2.y = h1;
    __nv_bfloat162 lo2;
    lo2.x = __float2bfloat16(v0 - __bfloat162float(h0));
    lo2.y = __float2bfloat16(v1 - __bfloat162float(h1));
    __nv_bfloat162* base = (__nv_bfloat162*)(g_A + (size_t)row * ASTRIDE);
    base[p]       = hi2;
    base[128 + p] = lo2;
}

// B rows n: [W_hi(k) | W_lo(k) | W_hi(k)], K-major [n][k], K=768
__global__ void bbuild_kernel(const float* __restrict__ W1) {
    int idx = blockIdx.x * blockDim.x + threadIdx.x;
    if (idx >= C * C) return;
    int nn = idx >> 8, k = idx & 255;
    float w = W1[(size_t)k * C + nn];
    __nv_bfloat16 hi = __float2bfloat16(w);
    __nv_bfloat16 lo = __float2bfloat16(w - __bfloat162float(hi));
    g_B[(size_t)nn * KSPL + k]       = hi;
    g_B[(size_t)nn * KSPL + 256 + k] = lo;
    g_B[(size_t)nn * KSPL + 512 + k] = hi;
}

// ---------------------------------------------------------------------------
// bf16 mma.sync GEMM with cp.async double buffering; epilogue packs bf16x2.
#define APAD 72
#define STG_ELEMS ((128 + 256) * APAD)

__device__ __forceinline__ void load_stage(uint32_t sbase, int tid, int m0,
                                           int kc, int s) {
    uint32_t As = sbase + (uint32_t)(s * STG_ELEMS) * 2;
    uint32_t Bs = As + 128 * APAD * 2;
    int aoff = (kc & 3) * 64 + ((kc >= 8) ? 256 : 0);   // hi chunks reused
    const __nv_bfloat16* Ab = g_A + (size_t)m0 * ASTRIDE + aoff;
    #pragma unroll
    for (int i = 0; i < 4; i++) {
        int u = tid + i * 256;
        int r = u >> 3, o = u & 7;
        cp16(As + (uint32_t)(r * APAD + o * 8) * 2,
             Ab + (size_t)r * ASTRIDE + o * 8);
    }
    const __nv_bfloat16* Bb = g_B + kc * 64;
    #pragma unroll
    for (int i = 0; i < 8; i++) {
        int u = tid + i * 256;
        int r = u >> 3, o = u & 7;
        cp16(Bs + (uint32_t)(r * APAD + o * 8) * 2,
             Bb + (size_t)r * KSPL + o * 8);
    }
    CP_COMMIT();
}

__global__ void __launch_bounds__(256) gemm_mma_kernel() {
    extern __shared__ __nv_bfloat16 smem[];

    int tid = threadIdx.x;
    int wid = tid >> 5, lane = tid & 31;
    int g = lane >> 2, tir = lane & 3;
    int wm = wid & 1, wn = wid >> 1;          // warp grid 2 x 4
    int m0 = blockIdx.x * 128;

    uint32_t sbase = smem_u32(smem);
    const int NKC = KSPL / 64;                // 12 chunks

    float c[4][8][4];
    #pragma unroll
    for (int mt = 0; mt < 4; mt++)
        #pragma unroll
        for (int nt = 0; nt < 8; nt++)
            #pragma unroll
            for (int q = 0; q < 4; q++) c[mt][nt][q] = 0.f;

    load_stage(sbase, tid, m0, 0, 0);

    for (int kc = 0; kc < NKC; kc++) {
        if (kc + 1 < NKC) {
            load_stage(sbase, tid, m0, kc + 1, (kc + 1) & 1);
            CP_WAIT(1);
        } else {
            CP_WAIT(0);
        }
        __syncthreads();

        const __nv_bfloat16* As = smem + (kc & 1) * STG_ELEMS;
        const __nv_bfloat16* Bs = As + 128 * APAD;

        #pragma unroll
        for (int ks = 0; ks < 4; ks++) {
            int kof = ks * 16 + tir * 2;
            uint32_t a[4][4];
            #pragma unroll
            for (int mt = 0; mt < 4; mt++) {
                int base = (wm * 64 + mt * 16 + g) * APAD + kof;
                a[mt][0] = *(const uint32_t*)(As + base);
                a[mt][1] = *(const uint32_t*)(As + base + 8 * APAD);
                a[mt][2] = *(const uint32_t*)(As + base + 8);
                a[mt][3] = *(const uint32_t*)(As + base + 8 * APAD + 8);
            }
            uint32_t b[8][2];
            #pragma unroll
            for (int nt = 0; nt < 8; nt++) {
                int base = (wn * 64 + nt * 8 + g) * APAD + kof;
                b[nt][0] = *(const uint32_t*)(Bs + base);
                b[nt][1] = *(const uint32_t*)(Bs + base + 8);
            }
            #pragma unroll
            for (int mt = 0; mt < 4; mt++)
                #pragma unroll
                for (int nt = 0; nt < 8; nt++)
                    mma16816(c[mt][nt], a[mt], b[nt]);
        }
        __syncthreads();
    }

    // epilogue: pack fp32 pair -> bf16x2, single 4B store per fragment half
    #pragma unroll
    for (int mt = 0; mt < 4; mt++) {
        int row = m0 + wm * 64 + mt * 16 + g;
        #pragma unroll
        for (int nt = 0; nt < 8; nt++) {
            int col2 = wn * 32 + nt * 4 + tir;   // (col)/2, col even
            __nv_bfloat162 p0 = __float22bfloat162_rn(
                make_float2(c[mt][nt][0], c[mt][nt][1]));
            __nv_bfloat162 p1 = __float22bfloat162_rn(
                make_float2(c[mt][nt][2], c[mt][nt][3]));
            g_hsb[(size_t)row * (C / 2) + col2]       = *(uint32_t*)&p0;
            g_hsb[(size_t)(row + 8) * (C / 2) + col2] = *(uint32_t*)&p1;
        }
    }
}

// ---------------------------------------------------------------------------
// fused CSR gather + relu + sorted-run mean-pool: one block per 64 nodes,
// 128 threads, thread t owns bf16x2 channel pair (2t, 2t+1). Pool sums are
// register-accumulated across the sorted batch run; atomics only on run
// boundaries (~0.4M total, vs 25.6M per-node atomics that storm the L2).
#define NPB 64
__global__ void __launch_bounds__(128) gather_pool_kernel(
        const void* __restrict__ batch, const float* __restrict__ b1, int n) {
    int t = threadIdx.x;                 // 0..127
    int start = blockIdx.x * NPB;
    if (start >= n) return;
    int end = min(start + NPB, n);
    int is64 = g_is64;

    float bx = b1[2 * t], by = b1[2 * t + 1];
    int gp = load_idx(batch, start, is64);
    float accx = 0.f, accy = 0.f;

    for (int i = start; i < end; i++) {
        int gid = load_idx(batch, i, is64);
        if (gid != gp) {
            atomicAdd(&g_sums[gp * C + 2 * t], accx);
            atomicAdd(&g_sums[gp * C + 2 * t + 1], accy);
            accx = 0.f; accy = 0.f; gp = gid;
        }

        int r0 = g_rowptr[i], r1 = g_rowptr[i + 1];
        uint32_t w = g_hsb[(size_t)i * 128 + t];      // self-loop
        float2 f = __bfloat1622float2(*(__nv_bfloat162*)&w);
        float a0x = f.x, a0y = f.y;
        float a1x = 0.f, a1y = 0.f, a2x = 0.f, a2y = 0.f, a3x = 0.f, a3y = 0.f;

        int j = r0;
        for (; j + 4 <= r1; j += 4) {
            int s0 = g_elist[j],     s1 = g_elist[j + 1];
            int s2 = g_elist[j + 2], s3 = g_elist[j + 3];
            uint32_t w0 = g_hsb[(size_t)s0 * 128 + t];
            uint32_t w1 = g_hsb[(size_t)s1 * 128 + t];
            uint32_t w2 = g_hsb[(size_t)s2 * 128 + t];
            uint32_t w3 = g_hsb[(size_t)s3 * 128 + t];
            float2 f0 = __bfloat1622float2(*(__nv_bfloat162*)&w0);
            float2 f1 = __bfloat1622float2(*(__nv_bfloat162*)&w1);
            float2 f2 = __bfloat1622float2(*(__nv_bfloat162*)&w2);
            float2 f3 = __bfloat1622float2(*(__nv_bfloat162*)&w3);
            a0x += f0.x; a0y += f0.y;
            a1x += f1.x; a1y += f1.y;
            a2x += f2.x; a2y += f2.y;
            a3x += f3.x; a3y += f3.y;
        }
        for (; j < r1; j++) {
            uint32_t wj = g_hsb[(size_t)g_elist[j] * 128 + t];
            float2 fj = __bfloat1622float2(*(__nv_bfloat162*)&wj);
            a0x += fj.x; a0y += fj.y;
        }

        float di = g_dinv[i];
        accx += fmaxf(di * ((a0x + a1x) + (a2x + a3x)) + bx, 0.f);
        accy += fmaxf(di * ((a0y + a1y) + (a2y + a3y)) + by, 0.f);
    }
    atomicAdd(&g_sums[gp * C + 2 * t], accx);
    atomicAdd(&g_sums[gp * C + 2 * t + 1], accy);
}

// ---------------------------------------------------------------------------
// counts: register run-length accumulation, one warp covers 32*64 nodes
__global__ void bcount_kernel(const void* __restrict__ batch, int n) {
    int lane = threadIdx.x & 31;
    int seg = (blockIdx.x * blockDim.x + threadIdx.x);   // one thread per 64
    int start = seg * 64;
    if (start >= n) return;
    int end = min(start + 64, n);
    int is64 = g_is64;
    int gp = load_idx(batch, start, is64);
    float cnt = 0.f;
    for (int i = start; i < end; i++) {
        int g = load_idx(batch, i, is64);
        if (g != gp) { atomicAdd(&g_counts[gp], cnt); cnt = 0.f; gp = g; }
        cnt += 1.f;
    }
    atomicAdd(&g_counts[gp], cnt);
    (void)lane;
}

__global__ void final_kernel(const float* __restrict__ W2,
                             const float* __restrict__ b2,
                             float* __restrict__ out) {
    int t = threadIdx.x;
    if (t >= GRAPHS * OUTC) return;
    int g = t / OUTC, o = t % OUTC;
    float s = 0.f;
    #pragma unroll 8
    for (int k = 0; k < C; k++)
        s += g_sums[g * C + k] * W2[k * OUTC + o];
    out[t] = s / fmaxf(g_counts[g], 1.f) + b2[o];
}

// ---------------------------------------------------------------------------
extern "C" void kernel_launch(void* const* d_in, const int* in_sizes, int n_in,
                              void* d_out, int out_size) {
    const float* x     = (const float*)d_in[0];
    const void*  ei    = d_in[1];
    const void*  batch = d_in[2];
    const float* W1    = (const float*)d_in[3];
    const float* b1    = (const float*)d_in[4];
    const float* W2    = (const float*)d_in[5];
    const float* b2    = (const float*)d_in[6];
    float* out = (float*)d_out;

    int n = in_sizes[0] / C;    // 100000
    int E = in_sizes[1] / 2;    // 1600000
    int nb = (n + 1023) / 1024;

    detect_kernel<<<1, 32>>>((const int*)ei);
    init_kernel<<<(n + 255) / 256, 256>>>(n);
    degi_kernel<<<(E + 255) / 256, 256>>>(ei, E);
    scan1_kernel<<<nb, 1024>>>(n);
    scan2_kernel<<<1, 1024>>>(nb);
    scan3_kernel<<<(n + 255) / 256, 256>>>(n);

    convert_kernel<<<(NODES_PAD * 128 + 255) / 256, 256>>>(x, n);
    bbuild_kernel<<<256, 256>>>(W1);

    static const int SMEM_BYTES = 2 * STG_ELEMS * 2;   // 110592
    cudaFuncSetAttribute(gemm_mma_kernel,
                         cudaFuncAttributeMaxDynamicSharedMemorySize, SMEM_BYTES);
    gemm_mma_kernel<<<NODES_PAD / 128, 256, SMEM_BYTES>>>();

    place_kernel<<<(E + 255) / 256, 256>>>(ei, E);
    bcount_kernel<<<(n / 64 + 255) / 256, 256>>>(batch, n);
    gather_pool_kernel<<<(n + NPB - 1) / NPB, 128>>>(batch, b1, n);
    final_kernel<<<1, 640>>>(W2, b2, out);
}

// round 9
// speedup vs baseline: 2.5695x; 1.2111x over previous
#include <cuda_runtime.h>
#include <cuda_bf16.h>
#include <cstdint>

#define NODES    100000
#define NODES_PAD 100096          // 782 * 128
#define C        256
#define GRAPHS   64
#define OUTC     10
#define EMAX     1600000
#define NB1024   ((NODES + 1023) / 1024)

// ---------------- scratch (static device globals; no allocation) ----------
__device__ __align__(16) __nv_bfloat16 g_A[(size_t)NODES_PAD * C];  // bf16(x*dinv)
__device__ __align__(16) __nv_bfloat16 g_B[(size_t)C * C];          // bf16(W1^T)
__device__ __align__(16) uint32_t g_hsb[(size_t)NODES_PAD * (C / 2)]; // bf16x2
__device__ float g_dinv[NODES];
__device__ int   g_degi[NODES];
__device__ int   g_rowptr[NODES + 1];
__device__ int   g_cursor[NODES];
__device__ int   g_elist[EMAX];
__device__ int   g_bsum[NB1024 + 1];
__device__ float g_sums[GRAPHS * C];
__device__ float g_counts[GRAPHS];
__device__ int   g_is64;

// ---------------- helpers ------------------------------------------------
__device__ __forceinline__ int load_idx(const void* p, long long i, int is64) {
    if (is64) return (int)((const long long*)p)[i];
    return ((const int*)p)[i];
}

__device__ __forceinline__ void mma16816(float* c, const uint32_t* a,
                                         const uint32_t* b) {
    asm volatile(
        "mma.sync.aligned.m16n8k16.row.col.f32.bf16.bf16.f32 "
        "{%0,%1,%2,%3}, {%4,%5,%6,%7}, {%8,%9}, {%0,%1,%2,%3};"
        : "+f"(c[0]), "+f"(c[1]), "+f"(c[2]), "+f"(c[3])
        : "r"(a[0]), "r"(a[1]), "r"(a[2]), "r"(a[3]), "r"(b[0]), "r"(b[1]));
}

__device__ __forceinline__ uint32_t smem_u32(const void* p) {
    uint32_t a;
    asm("{ .reg .u64 t; cvta.to.shared.u64 t, %1; cvt.u32.u64 %0, t; }"
        : "=r"(a) : "l"(p));
    return a;
}
__device__ __forceinline__ void cp16(uint32_t dst, const void* src) {
    asm volatile("cp.async.ca.shared.global [%0], [%1], 16;"
                 :: "r"(dst), "l"(src) : "memory");
}
#define CP_COMMIT() asm volatile("cp.async.commit_group;" ::: "memory")
#define CP_WAIT(N)  asm volatile("cp.async.wait_group %0;" :: "n"(N) : "memory")

// ---------------------------------------------------------------------------
__global__ void detect_kernel(const int* __restrict__ ei32) {
    if (threadIdx.x == 0 && blockIdx.x == 0) {
        int nz = 0;
        #pragma unroll
        for (int i = 1; i < 256; i += 2) nz |= (ei32[i] != 0);
        g_is64 = (nz == 0) ? 1 : 0;
    }
}

__global__ void init_kernel(int n) {
    int i = blockIdx.x * blockDim.x + threadIdx.x;
    if (i < n) g_degi[i] = 0;
    if (i < GRAPHS * C) g_sums[i] = 0.f;
    if (i < GRAPHS) g_counts[i] = 0.f;
}

__global__ void degi_kernel(const void* __restrict__ ei, int E) {
    int i = blockIdx.x * blockDim.x + threadIdx.x;
    if (i >= E) return;
    int d = load_idx(ei, (long long)E + i, g_is64);
    atomicAdd(&g_degi[d], 1);
}

// ---------------- hierarchical scan ----------------------------------------
__global__ void scan1_kernel(int n) {
    __shared__ int wsum[32];
    int t = threadIdx.x;
    int i = blockIdx.x * 1024 + t;
    int v = (i < n) ? g_degi[i] : 0;
    int lane = t & 31, w = t >> 5;
    int inc = v;
    #pragma unroll
    for (int d = 1; d < 32; d <<= 1) {
        int u = __shfl_up_sync(0xFFFFFFFFu, inc, d);
        if (lane >= d) inc += u;
    }
    if (lane == 31) wsum[w] = inc;
    __syncthreads();
    if (w == 0) {
        int x = wsum[lane];
        #pragma unroll
        for (int d = 1; d < 32; d <<= 1) {
            int u = __shfl_up_sync(0xFFFFFFFFu, x, d);
            if (lane >= d) x += u;
        }
        wsum[lane] = x;
    }
    __syncthreads();
    int excl = inc - v + (w ? wsum[w - 1] : 0);
    if (i < n) g_rowptr[i] = excl;
    if (t == 1023) g_bsum[blockIdx.x] = excl + v;
}

__global__ void scan2_kernel(int nb) {
    __shared__ int wsum[32];
    int t = threadIdx.x;                     // 1024 threads
    int v = (t < nb) ? g_bsum[t] : 0;
    int lane = t & 31, w = t >> 5;
    int inc = v;
    #pragma unroll
    for (int d = 1; d < 32; d <<= 1) {
        int u = __shfl_up_sync(0xFFFFFFFFu, inc, d);
        if (lane >= d) inc += u;
    }
    if (lane == 31) wsum[w] = inc;
    __syncthreads();
    if (w == 0) {
        int x = wsum[lane];
        #pragma unroll
        for (int d = 1; d < 32; d <<= 1) {
            int u = __shfl_up_sync(0xFFFFFFFFu, x, d);
            if (lane >= d) x += u;
        }
        wsum[lane] = x;
    }
    __syncthreads();
    int excl = inc - v + (w ? wsum[w - 1] : 0);
    if (t < nb) g_bsum[t] = excl;
}

__global__ void scan3_kernel(int n) {
    int i = blockIdx.x * blockDim.x + threadIdx.x;
    if (i >= n) return;
    int d = g_degi[i];
    int r = g_rowptr[i] + g_bsum[i >> 10];
    g_rowptr[i] = r;
    g_cursor[i] = r;
    g_dinv[i] = rsqrtf((float)d + 1.f);
    if (i == n - 1) g_rowptr[n] = r + d;
}

__global__ void place_kernel(const void* __restrict__ ei, int E) {
    int e = blockIdx.x * blockDim.x + threadIdx.x;
    if (e >= E) return;
    int is64 = g_is64;
    int src = load_idx(ei, e, is64);
    int dst = load_idx(ei, (long long)E + e, is64);
    int pos = atomicAdd(&g_cursor[dst], 1);
    g_elist[pos] = src;
}

// ---------------------------------------------------------------------------
// A = bf16(x * dinv[row]), rows >= n zero-padded
__global__ void convert_kernel(const float* __restrict__ x, int n) {
    long long idx = (long long)blockIdx.x * blockDim.x + threadIdx.x;
    if (idx >= (long long)NODES_PAD * 128) return;
    int row = (int)(idx >> 7);
    int p = (int)(idx & 127);
    int c = p * 2;
    float v0 = 0.f, v1 = 0.f;
    if (row < n) {
        float d = g_dinv[row];
        v0 = x[(size_t)row * C + c] * d;
        v1 = x[(size_t)row * C + c + 1] * d;
    }
    __nv_bfloat162 hi2 = __float22bfloat162_rn(make_float2(v0, v1));
    ((__nv_bfloat162*)(g_A + (size_t)row * C))[p] = hi2;
}

// B rows nn: bf16(W1[:, nn]), K-major [nn][k]
__global__ void bbuild_kernel(const float* __restrict__ W1) {
    int idx = blockIdx.x * blockDim.x + threadIdx.x;
    if (idx >= C * C) return;
    int nn = idx >> 8, k = idx & 255;
    g_B[(size_t)nn * C + k] = __float2bfloat16(W1[(size_t)k * C + nn]);
}

// ---------------------------------------------------------------------------
// bf16 mma.sync GEMM, K=256, cp.async double buffered; epilogue packs bf16x2.
#define APAD 72
#define STG_ELEMS ((128 + 256) * APAD)

__device__ __forceinline__ void load_stage(uint32_t sbase, int tid, int m0,
                                           int kc, int s) {
    uint32_t As = sbase + (uint32_t)(s * STG_ELEMS) * 2;
    uint32_t Bs = As + 128 * APAD * 2;
    const __nv_bfloat16* Ab = g_A + (size_t)m0 * C + kc * 64;
    #pragma unroll
    for (int i = 0; i < 4; i++) {
        int u = tid + i * 256;
        int r = u >> 3, o = u & 7;
        cp16(As + (uint32_t)(r * APAD + o * 8) * 2,
             Ab + (size_t)r * C + o * 8);
    }
    const __nv_bfloat16* Bb = g_B + kc * 64;
    #pragma unroll
    for (int i = 0; i < 8; i++) {
        int u = tid + i * 256;
        int r = u >> 3, o = u & 7;
        cp16(Bs + (uint32_t)(r * APAD + o * 8) * 2,
             Bb + (size_t)r * C + o * 8);
    }
    CP_COMMIT();
}

__global__ void __launch_bounds__(256) gemm_mma_kernel() {
    extern __shared__ __nv_bfloat16 smem[];

    int tid = threadIdx.x;
    int wid = tid >> 5, lane = tid & 31;
    int g = lane >> 2, tir = lane & 3;
    int wm = wid & 1, wn = wid >> 1;          // warp grid 2 x 4
    int m0 = blockIdx.x * 128;

    uint32_t sbase = smem_u32(smem);
    const int NKC = C / 64;                   // 4 chunks

    float c[4][8][4];
    #pragma unroll
    for (int mt = 0; mt < 4; mt++)
        #pragma unroll
        for (int nt = 0; nt < 8; nt++)
            #pragma unroll
            for (int q = 0; q < 4; q++) c[mt][nt][q] = 0.f;

    load_stage(sbase, tid, m0, 0, 0);

    for (int kc = 0; kc < NKC; kc++) {
        if (kc + 1 < NKC) {
            load_stage(sbase, tid, m0, kc + 1, (kc + 1) & 1);
            CP_WAIT(1);
        } else {
            CP_WAIT(0);
        }
        __syncthreads();

        const __nv_bfloat16* As = smem + (kc & 1) * STG_ELEMS;
        const __nv_bfloat16* Bs = As + 128 * APAD;

        #pragma unroll
        for (int ks = 0; ks < 4; ks++) {
            int kof = ks * 16 + tir * 2;
            uint32_t a[4][4];
            #pragma unroll
            for (int mt = 0; mt < 4; mt++) {
                int base = (wm * 64 + mt * 16 + g) * APAD + kof;
                a[mt][0] = *(const uint32_t*)(As + base);
                a[mt][1] = *(const uint32_t*)(As + base + 8 * APAD);
                a[mt][2] = *(const uint32_t*)(As + base + 8);
                a[mt][3] = *(const uint32_t*)(As + base + 8 * APAD + 8);
            }
            uint32_t b[8][2];
            #pragma unroll
            for (int nt = 0; nt < 8; nt++) {
                int base = (wn * 64 + nt * 8 + g) * APAD + kof;
                b[nt][0] = *(const uint32_t*)(Bs + base);
                b[nt][1] = *(const uint32_t*)(Bs + base + 8);
            }
            #pragma unroll
            for (int mt = 0; mt < 4; mt++)
                #pragma unroll
                for (int nt = 0; nt < 8; nt++)
                    mma16816(c[mt][nt], a[mt], b[nt]);
        }
        __syncthreads();
    }

    // epilogue: pack fp32 pair -> bf16x2, single 4B store per fragment half
    #pragma unroll
    for (int mt = 0; mt < 4; mt++) {
        int row = m0 + wm * 64 + mt * 16 + g;
        #pragma unroll
        for (int nt = 0; nt < 8; nt++) {
            int col2 = wn * 32 + nt * 4 + tir;   // (col)/2, col even
            __nv_bfloat162 p0 = __float22bfloat162_rn(
                make_float2(c[mt][nt][0], c[mt][nt][1]));
            __nv_bfloat162 p1 = __float22bfloat162_rn(
                make_float2(c[mt][nt][2], c[mt][nt][3]));
            g_hsb[(size_t)row * (C / 2) + col2]       = *(uint32_t*)&p0;
            g_hsb[(size_t)(row + 8) * (C / 2) + col2] = *(uint32_t*)&p1;
        }
    }
}

// ---------------------------------------------------------------------------
// fused CSR gather + relu + sorted-run mean-pool: one block per 64 nodes,
// 128 threads, thread t owns bf16x2 channel pair (2t, 2t+1). Pool sums are
// register-accumulated across the sorted batch run; atomics only on run
// boundaries (~0.4M total, vs 25.6M per-node atomics that storm the L2).
#define NPB 64
__global__ void __launch_bounds__(128) gather_pool_kernel(
        const void* __restrict__ batch, const float* __restrict__ b1, int n) {
    int t = threadIdx.x;                 // 0..127
    int start = blockIdx.x * NPB;
    if (start >= n) return;
    int end = min(start + NPB, n);
    int is64 = g_is64;

    float bx = b1[2 * t], by = b1[2 * t + 1];
    int gp = load_idx(batch, start, is64);
    float accx = 0.f, accy = 0.f;

    for (int i = start; i < end; i++) {
        int gid = load_idx(batch, i, is64);
        if (gid != gp) {
            atomicAdd(&g_sums[gp * C + 2 * t], accx);
            atomicAdd(&g_sums[gp * C + 2 * t + 1], accy);
            accx = 0.f; accy = 0.f; gp = gid;
        }

        int r0 = g_rowptr[i], r1 = g_rowptr[i + 1];
        uint32_t w = g_hsb[(size_t)i * 128 + t];      // self-loop
        float2 f = __bfloat1622float2(*(__nv_bfloat162*)&w);
        float a0x = f.x, a0y = f.y;
        float a1x = 0.f, a1y = 0.f, a2x = 0.f, a2y = 0.f, a3x = 0.f, a3y = 0.f;

        int j = r0;
        for (; j + 4 <= r1; j += 4) {
            int s0 = g_elist[j],     s1 = g_elist[j + 1];
            int s2 = g_elist[j + 2], s3 = g_elist[j + 3];
            uint32_t w0 = g_hsb[(size_t)s0 * 128 + t];
            uint32_t w1 = g_hsb[(size_t)s1 * 128 + t];
            uint32_t w2 = g_hsb[(size_t)s2 * 128 + t];
            uint32_t w3 = g_hsb[(size_t)s3 * 128 + t];
            float2 f0 = __bfloat1622float2(*(__nv_bfloat162*)&w0);
            float2 f1 = __bfloat1622float2(*(__nv_bfloat162*)&w1);
            float2 f2 = __bfloat1622float2(*(__nv_bfloat162*)&w2);
            float2 f3 = __bfloat1622float2(*(__nv_bfloat162*)&w3);
            a0x += f0.x; a0y += f0.y;
            a1x += f1.x; a1y += f1.y;
            a2x += f2.x; a2y += f2.y;
            a3x += f3.x; a3y += f3.y;
        }
        for (; j < r1; j++) {
            uint32_t wj = g_hsb[(size_t)g_elist[j] * 128 + t];
            float2 fj = __bfloat1622float2(*(__nv_bfloat162*)&wj);
            a0x += fj.x; a0y += fj.y;
        }

        float di = g_dinv[i];
        accx += fmaxf(di * ((a0x + a1x) + (a2x + a3x)) + bx, 0.f);
        accy += fmaxf(di * ((a0y + a1y) + (a2y + a3y)) + by, 0.f);
    }
    atomicAdd(&g_sums[gp * C + 2 * t], accx);
    atomicAdd(&g_sums[gp * C + 2 * t + 1], accy);
}

// ---------------------------------------------------------------------------
// counts: register run-length accumulation, one thread per 64 nodes
__global__ void bcount_kernel(const void* __restrict__ batch, int n) {
    int seg = (blockIdx.x * blockDim.x + threadIdx.x);
    int start = seg * 64;
    if (start >= n) return;
    int end = min(start + 64, n);
    int is64 = g_is64;
    int gp = load_idx(batch, start, is64);
    float cnt = 0.f;
    for (int i = start; i < end; i++) {
        int g = load_idx(batch, i, is64);
        if (g != gp) { atomicAdd(&g_counts[gp], cnt); cnt = 0.f; gp = g; }
        cnt += 1.f;
    }
    atomicAdd(&g_counts[gp], cnt);
}

__global__ void final_kernel(const float* __restrict__ W2,
                             const float* __restrict__ b2,
                             float* __restrict__ out) {
    int t = threadIdx.x;
    if (t >= GRAPHS * OUTC) return;
    int g = t / OUTC, o = t % OUTC;
    float s = 0.f;
    #pragma unroll 8
    for (int k = 0; k < C; k++)
        s += g_sums[g * C + k] * W2[k * OUTC + o];
    out[t] = s / fmaxf(g_counts[g], 1.f) + b2[o];
}

// ---------------------------------------------------------------------------
extern "C" void kernel_launch(void* const* d_in, const int* in_sizes, int n_in,
                              void* d_out, int out_size) {
    const float* x     = (const float*)d_in[0];
    const void*  ei    = d_in[1];
    const void*  batch = d_in[2];
    const float* W1    = (const float*)d_in[3];
    const float* b1    = (const float*)d_in[4];
    const float* W2    = (const float*)d_in[5];
    const float* b2    = (const float*)d_in[6];
    float* out = (float*)d_out;

    int n = in_sizes[0] / C;    // 100000
    int E = in_sizes[1] / 2;    // 1600000
    int nb = (n + 1023) / 1024;

    detect_kernel<<<1, 32>>>((const int*)ei);
    init_kernel<<<(n + 255) / 256, 256>>>(n);
    degi_kernel<<<(E + 255) / 256, 256>>>(ei, E);
    scan1_kernel<<<nb, 1024>>>(n);
    scan2_kernel<<<1, 1024>>>(nb);
    scan3_kernel<<<(n + 255) / 256, 256>>>(n);

    convert_kernel<<<(NODES_PAD * 128 + 255) / 256, 256>>>(x, n);
    bbuild_kernel<<<256, 256>>>(W1);

    static const int SMEM_BYTES = 2 * STG_ELEMS * 2;   // 110592
    cudaFuncSetAttribute(gemm_mma_kernel,
                         cudaFuncAttributeMaxDynamicSharedMemorySize, SMEM_BYTES);
    gemm_mma_kernel<<<NODES_PAD / 128, 256, SMEM_BYTES>>>();

    place_kernel<<<(E + 255) / 256, 256>>>(ei, E);
    bcount_kernel<<<(n / 64 + 255) / 256, 256>>>(batch, n);
    gather_pool_kernel<<<(n + NPB - 1) / NPB, 128>>>(batch, b1, n);
    final_kernel<<<1, 640>>>(W2, b2, out);
}